// round 16
// baseline (speedup 1.0000x reference)
#include <cuda_runtime.h>
#include <cuda_fp16.h>
#include <cstdint>

#define BB 4
#define NN 2048
#define KK 32
#define L0 128
#define L1C 128
#define L2C 256
#define PTOT (BB*NN*KK)   /* 262144 */
#define EPSV 1e-5f
#define SLOPE 0.01f

// ---------------- scratch ----------------
__device__ __align__(16) float g_A[BB*NN*L0];              // 4 MB fp32
__device__ __align__(16) float g_D[BB*NN*L0];              // 4 MB fp32
__device__ __align__(16) uint32_t g_Ah[BB*NN*64];          // 2 MB : a0*A, half2 (folded)
__device__ __align__(16) uint32_t g_Dh[BB*NN*64];          // 2 MB : a0*D + c0, half2
__device__ __align__(16) char g_y1s[(size_t)4096*16384];   // 67 MB : y1, swizzled 16KB tiles
__device__ float g_mx[BB*NN*L2C];            // 8 MB
__device__ float g_mn[BB*NN*L2C];            // 8 MB
__device__ float g_s0[2*L0];
__device__ float g_s1[2*L1C];
__device__ float g_s2[2*L2C];
__device__ __align__(16) uint32_t g_W1h2[128*64];          // W1 fp16 half2
__device__ __align__(16) uint32_t g_W2h2[256*64];          // W2 fp16 half2

// ---------------- helpers ----------------
__device__ __forceinline__ uint32_t smem_u32(const void* p) {
    uint32_t a;
    asm("{ .reg .u64 t; cvta.to.shared.u64 t, %1; cvt.u32.u64 %0, t; }" : "=r"(a) : "l"(p));
    return a;
}
__device__ __forceinline__ void ldmx4(uint32_t* r, uint32_t addr) {
    asm volatile("ldmatrix.sync.aligned.m8n8.x4.shared.b16 {%0,%1,%2,%3}, [%4];"
                 : "=r"(r[0]), "=r"(r[1]), "=r"(r[2]), "=r"(r[3]) : "r"(addr));
}
__device__ __forceinline__ void mma16816(float* d, const uint32_t* a, const uint32_t* b) {
    asm volatile(
        "mma.sync.aligned.m16n8k16.row.col.f32.f16.f16.f32 "
        "{%0,%1,%2,%3}, {%4,%5,%6,%7}, {%8,%9}, {%0,%1,%2,%3};"
        : "+f"(d[0]), "+f"(d[1]), "+f"(d[2]), "+f"(d[3])
        : "r"(a[0]), "r"(a[1]), "r"(a[2]), "r"(a[3]), "r"(b[0]), "r"(b[1]));
}
__device__ __forceinline__ void cp16(uint32_t dst, const void* src) {
    asm volatile("cp.async.cg.shared.global [%0], [%1], 16;" :: "r"(dst), "l"(src));
}
#define CP_COMMIT() asm volatile("cp.async.commit_group;" ::: "memory")
#define CP_WAIT0()  asm volatile("cp.async.wait_group 0;" ::: "memory")
// tile rows are 256B (128 halves); XOR-swizzle 16B chunks within each 128B octant
__device__ __forceinline__ uint32_t sw_pair(int row, int c2) {   // c2 = half2 index 0..63
    return (uint32_t)row*256u + (uint32_t)(((c2 >> 2) ^ (row & 7)) << 4) + (uint32_t)((c2 & 3) << 2);
}
__device__ __forceinline__ uint32_t sw_chunk(int row, int cl) {  // cl = 16B chunk 0..15
    return (uint32_t)row*256u + (uint32_t)(((cl ^ (row & 7)) & 15) << 4);
}
__device__ __forceinline__ uint32_t add_lrelu2(uint32_t a, uint32_t d) {
    __half2 s = __hadd2(*(__half2*)&a, *(__half2*)&d);
    __half2 u = __hmax2(s, __hmul2(s, __float2half2_rn(SLOPE)));
    return *(uint32_t*)&u;
}
__device__ __forceinline__ uint32_t bn_lrelu2(uint32_t y, uint32_t a, uint32_t c) {
    __half2 u = __hfma2(*(__half2*)&a, *(__half2*)&y, *(__half2*)&c);
    __half2 r = __hmax2(u, __hmul2(u, __float2half2_rn(SLOPE)));
    return *(uint32_t*)&r;
}

// ---------------- k_prep: A/D factorization (fp32 out) + absorbed zero/W-split ----------------
#define SW_PITCH 16900   /* 131*129=16899 rounded up so sI is 16B-aligned */
static const int SMEM_PREP = (SW_PITCH + 131*16) * 4;
__global__ void __launch_bounds__(128) k_prep(
        const float* __restrict__ pos1, const float* __restrict__ pos2,
        const float* __restrict__ f1,   const float* __restrict__ f2,
        const float* __restrict__ W0,
        const float* __restrict__ W1,   const float* __restrict__ W2) {
    extern __shared__ float sp[];
    float* sW = sp;               // [131][129]
    float* sI = sp + SW_PITCH;    // [131][16], 16B-aligned
    int blk = blockIdx.x;
    int b  = blk / (NN/16);
    int j0 = (blk % (NN/16)) * 16;
    int tid = threadIdx.x;

    if (blk == 0) {
        for (int j = tid; j < 1024; j += 128) {
            if (j < 256)      g_s0[j] = 0.f;
            else if (j < 512) g_s1[j - 256] = 0.f;
            else              g_s2[j - 512] = 0.f;
        }
    }
    if (blk < 96) {
        for (int t2 = tid; t2 < 256; t2 += 128) {
            int i = blk * 256 + t2;
            if (i < 8192) {
                float2 w = ((const float2*)W1)[i];
                __half2 h = __floats2half2_rn(w.x, w.y);
                g_W1h2[i] = *(uint32_t*)&h;
            } else if (i < 24576) {
                int j = i - 8192;
                float2 w = ((const float2*)W2)[j];
                __half2 h = __floats2half2_rn(w.x, w.y);
                g_W2h2[j] = *(uint32_t*)&h;
            }
        }
    }

    // ---- pass A ----
    for (int i = tid; i < 131*128; i += 128) {
        int o = i / 131, c = i - o*131;
        sW[c*129 + o] = W0[o*259 + c];
    }
    for (int i = tid; i < 131*16; i += 128) {
        int c = i >> 4, jl = i & 15;
        sI[c*16 + jl] = (c < 3) ? pos2[(b*3 + c)*NN + j0 + jl]
                                : f2[(b*128 + (c-3))*NN + j0 + jl];
    }
    __syncthreads();
    {
        float4 acc[4];
        #pragma unroll
        for (int q = 0; q < 4; q++) acc[q] = make_float4(0.f,0.f,0.f,0.f);
        for (int c = 0; c < 131; c++) {
            float wv = sW[c*129 + tid];
            const float4* r = (const float4*)&sI[c*16];
            #pragma unroll
            for (int q = 0; q < 4; q++) {
                float4 rv = r[q];
                acc[q].x = fmaf(wv, rv.x, acc[q].x);
                acc[q].y = fmaf(wv, rv.y, acc[q].y);
                acc[q].z = fmaf(wv, rv.z, acc[q].z);
                acc[q].w = fmaf(wv, rv.w, acc[q].w);
            }
        }
        const float* af = (const float*)acc;
        #pragma unroll
        for (int pt = 0; pt < 16; pt++)
            g_A[((b*NN + j0 + pt) << 7) + tid] = af[pt];
    }
    __syncthreads();

    // ---- pass D ----
    for (int i = tid; i < 131*128; i += 128) {
        int o = i / 131, c = i - o*131;
        int src = (c < 3) ? c : 128 + c;   // 131 + (c-3)
        sW[c*129 + o] = W0[o*259 + src];
    }
    for (int i = tid; i < 131*16; i += 128) {
        int c = i >> 4, jl = i & 15;
        sI[c*16 + jl] = (c < 3) ? -pos1[(b*3 + c)*NN + j0 + jl]
                                : f1[(b*128 + (c-3))*NN + j0 + jl];
    }
    __syncthreads();
    {
        float4 acc[4];
        #pragma unroll
        for (int q = 0; q < 4; q++) acc[q] = make_float4(0.f,0.f,0.f,0.f);
        for (int c = 0; c < 131; c++) {
            float wv = sW[c*129 + tid];
            const float4* r = (const float4*)&sI[c*16];
            #pragma unroll
            for (int q = 0; q < 4; q++) {
                float4 rv = r[q];
                acc[q].x = fmaf(wv, rv.x, acc[q].x);
                acc[q].y = fmaf(wv, rv.y, acc[q].y);
                acc[q].z = fmaf(wv, rv.z, acc[q].z);
                acc[q].w = fmaf(wv, rv.w, acc[q].w);
            }
        }
        const float* af = (const float*)acc;
        #pragma unroll
        for (int pt = 0; pt < 16; pt++)
            g_D[((b*NN + j0 + pt) << 7) + tid] = af[pt];
    }
}

// ---------------- k_stats0: stats of y0 = A[idx] + D (R11 exact form) ----------------
__global__ void __launch_bounds__(128) k_stats0(const int* __restrict__ idxp) {
    __shared__ int s_idx[128];
    int tid = threadIdx.x;
    int pbase = blockIdx.x * 128;
    s_idx[tid] = idxp[pbase + tid];
    __syncthreads();
    float s = 0.f, ss = 0.f;
    #pragma unroll 4
    for (int i = 0; i < 128; i++) {
        int p = pbase + i;
        int arow = ((p >> 16) * NN + s_idx[i]) << 7;
        int drow = (p >> 5) << 7;
        float y = g_A[arow + tid] + g_D[drow + tid];
        s += y; ss = fmaf(y, y, ss);
    }
    atomicAdd(&g_s0[tid], s);
    atomicAdd(&g_s0[L0 + tid], ss);
}

// ---------------- k_fold: A~ = a0*A (half2), D~ = a0*D + c0 (half2) ----------------
__global__ void __launch_bounds__(256) k_fold(
        const float* __restrict__ gam, const float* __restrict__ bet) {
    __shared__ float sA[128], sC[128];
    int tid = threadIdx.x;
    if (tid < 128) {
        const float inv = 1.0f / (float)PTOT;
        float mean = g_s0[tid] * inv;
        float var  = g_s0[128 + tid] * inv - mean * mean;
        float a = gam[tid] * rsqrtf(var + EPSV);
        sA[tid] = a; sC[tid] = bet[tid] - mean * a;
    }
    __syncthreads();
    int q = blockIdx.x * 256 + tid;     // quad index over BB*NN*16
    int row = q >> 4, ch = q & 15;
    int c = ch << 3;
    const float4* a4 = (const float4*)(g_A + (row << 7) + c);
    const float4* d4 = (const float4*)(g_D + (row << 7) + c);
    float4 av0 = a4[0], av1 = a4[1], dv0 = d4[0], dv1 = d4[1];
    uint4 oa, od;
    {
        __half2 h;
        h = __floats2half2_rn(sA[c+0]*av0.x, sA[c+1]*av0.y); oa.x = *(uint32_t*)&h;
        h = __floats2half2_rn(sA[c+2]*av0.z, sA[c+3]*av0.w); oa.y = *(uint32_t*)&h;
        h = __floats2half2_rn(sA[c+4]*av1.x, sA[c+5]*av1.y); oa.z = *(uint32_t*)&h;
        h = __floats2half2_rn(sA[c+6]*av1.z, sA[c+7]*av1.w); oa.w = *(uint32_t*)&h;
        h = __floats2half2_rn(fmaf(sA[c+0],dv0.x,sC[c+0]), fmaf(sA[c+1],dv0.y,sC[c+1])); od.x = *(uint32_t*)&h;
        h = __floats2half2_rn(fmaf(sA[c+2],dv0.z,sC[c+2]), fmaf(sA[c+3],dv0.w,sC[c+3])); od.y = *(uint32_t*)&h;
        h = __floats2half2_rn(fmaf(sA[c+4],dv1.x,sC[c+4]), fmaf(sA[c+5],dv1.y,sC[c+5])); od.z = *(uint32_t*)&h;
        h = __floats2half2_rn(fmaf(sA[c+6],dv1.z,sC[c+6]), fmaf(sA[c+7],dv1.w,sC[c+7])); od.w = *(uint32_t*)&h;
    }
    *(uint4*)&g_Ah[(row << 6) + (ch << 2)] = oa;
    *(uint4*)&g_Dh[(row << 6) + (ch << 2)] = od;
}

// ======================= layer 1 =======================
// block: 256 pts x 128 out; ALL 4 U tiles resident (64KB); fill once, 1 barrier,
// then 4 barrier-free mma phases. 256 thr / 8 warps; 2 CTAs/SM.
static const int L1_U  = 4096;                // 4 x 16384 = 65536
static const int L1_WH = L1_U + 65536;        // 69632
static const int SMEM_L1 = L1_WH + 32768;     // 102400

__global__ void __launch_bounds__(256, 2) k_l1(const int* __restrict__ idxp) {
    extern __shared__ char sm[];
    uint32_t sb = smem_u32(sm);
    int*   sAR  = (int*)(sm);            // 256 ints
    float* sSum = (float*)(sm + 1024);   // 128
    float* sSs  = (float*)(sm + 1536);   // 128
    int tid = threadIdx.x, wid = tid >> 5, lane = tid & 31;
    int pblk = blockIdx.x * 256;

    if (tid < 128) { sSum[tid] = 0.f; sSs[tid] = 0.f; }
    {
        int p = pblk + tid;
        sAR[tid] = ((p >> 16) * NN + idxp[p]) << 6;
    }
    __syncthreads();

    // W tile
    for (int i = tid; i < 8192; i += 256) {
        int o = i >> 6, c2 = i & 63;
        *(uint32_t*)(sm + L1_WH + sw_pair(o, c2)) = g_W1h2[i];
    }

    int fch = tid & 15, fpl = tid >> 4;
    // fill ALL 4 tiles back-to-back (max MLP, one latency exposure)
    #pragma unroll
    for (int it = 0; it < 16; it++) {
        int r = fpl + it * 16;               // 0..255
        uint4 av = *(const uint4*)&g_Ah[sAR[r] + (fch << 2)];
        uint4 dv = *(const uint4*)&g_Dh[(((pblk + r) >> 5) << 6) + (fch << 2)];
        uint4 o;
        o.x = add_lrelu2(av.x, dv.x);
        o.y = add_lrelu2(av.y, dv.y);
        o.z = add_lrelu2(av.z, dv.z);
        o.w = add_lrelu2(av.w, dv.w);
        *(uint4*)(sm + L1_U + (r >> 6) * 16384 + sw_chunk(r & 63, fch)) = o;
    }
    __syncthreads();   // the ONLY barrier before compute

    int mr = (wid & 3) * 16, nr = (wid >> 2) * 64;
    int aRow = lane & 15, aSel = lane >> 4;
    int bRow = (lane & 7) + ((lane >> 4) << 3), bSel = (lane >> 3) & 1;

    #pragma unroll 1
    for (int t = 0; t < 4; t++) {
        int pbase = pblk + t * 64;
        uint32_t Ut = sb + L1_U + t * 16384;

        float acc[8][4];
        #pragma unroll
        for (int nt = 0; nt < 8; nt++)
            #pragma unroll
            for (int q = 0; q < 4; q++) acc[nt][q] = 0.f;

        for (int ks = 0; ks < 8; ks++) {
            uint32_t ah[4];
            int clA = 2*ks + aSel;
            ldmx4(ah, Ut + sw_chunk(mr + aRow, clA));
            int clB = 2*ks + bSel;
            #pragma unroll
            for (int q = 0; q < 4; q++) {
                int n = nr + q*16 + bRow;
                uint32_t bh[4];
                ldmx4(bh, sb + L1_WH + sw_chunk(n, clB));
                mma16816(acc[2*q],     ah, bh);
                mma16816(acc[2*q + 1], ah, bh + 2);
            }
        }

        // ---- epilogue (no barriers; overlaps next tile's mma) ----
        {
            int r = mr + (lane >> 2);
            char* yb = g_y1s + ((size_t)(pbase >> 6)) * 16384;
            #pragma unroll
            for (int nt = 0; nt < 8; nt++) {
                int c2 = (nr >> 1) + nt*4 + (lane & 3);
                __half2 h0 = __floats2half2_rn(acc[nt][0], acc[nt][1]);
                __half2 h1 = __floats2half2_rn(acc[nt][2], acc[nt][3]);
                *(uint32_t*)(yb + sw_pair(r, c2))     = *(uint32_t*)&h0;
                *(uint32_t*)(yb + sw_pair(r + 8, c2)) = *(uint32_t*)&h1;
            }
        }
        #pragma unroll
        for (int nt = 0; nt < 8; nt++) {
            float s0 = acc[nt][0] + acc[nt][2];
            float s1 = acc[nt][1] + acc[nt][3];
            float q0 = acc[nt][0]*acc[nt][0] + acc[nt][2]*acc[nt][2];
            float q1 = acc[nt][1]*acc[nt][1] + acc[nt][3]*acc[nt][3];
            #pragma unroll
            for (int d = 4; d < 32; d <<= 1) {
                s0 += __shfl_xor_sync(0xFFFFFFFF, s0, d);
                s1 += __shfl_xor_sync(0xFFFFFFFF, s1, d);
                q0 += __shfl_xor_sync(0xFFFFFFFF, q0, d);
                q1 += __shfl_xor_sync(0xFFFFFFFF, q1, d);
            }
            if (lane < 4) {
                int c = nr + nt*8 + (lane << 1);
                atomicAdd(&sSum[c], s0);  atomicAdd(&sSum[c + 1], s1);
                atomicAdd(&sSs[c],  q0);  atomicAdd(&sSs[c + 1],  q1);
            }
        }
    }
    __syncthreads();
    if (tid < 128) {
        atomicAdd(&g_s1[tid],       sSum[tid]);
        atomicAdd(&g_s1[128 + tid], sSs[tid]);
    }
}

// ======================= layer 2 =======================
// block: 256 pts x 128 out-half; ALL 4 y1 tiles cp.async'd upfront (64KB);
// one wait + 1 barrier, then 4 barrier-free mma phases (fragment BN). 2 CTAs/SM.
static const int L2_U  = 4096;                // 4 x 16384 = 65536
static const int L2_WH = L2_U + 65536;        // 69632
static const int SMEM_L2 = L2_WH + 32768;     // 102400

__global__ void __launch_bounds__(256, 2) k_l2(
        const float* __restrict__ gam, const float* __restrict__ bet) {
    extern __shared__ char sm[];
    uint32_t sb = smem_u32(sm);
    uint2* sAC  = (uint2*)(sm);          // 64 x {a half2, c half2}
    float* sSum = (float*)(sm + 512);    // 128
    float* sSs  = (float*)(sm + 1024);   // 128
    int tid = threadIdx.x, wid = tid >> 5, lane = tid & 31;
    int tb = (blockIdx.x >> 1) * 4;      // tile base (64-pt tiles)
    int nh = (blockIdx.x & 1) * 128;

    // issue ALL cp.async copies first (16 x 16B per thread)
    {
        const char* src0 = g_y1s + (size_t)tb * 16384 + tid * 16;
        uint32_t dst0 = sb + L2_U + tid * 16;
        #pragma unroll
        for (int t = 0; t < 4; t++)
            #pragma unroll
            for (int k2 = 0; k2 < 4; k2++)
                cp16(dst0 + t*16384 + k2*4096, src0 + (size_t)t*16384 + k2*4096);
        CP_COMMIT();
    }

    if (tid < 128) { sSum[tid] = 0.f; sSs[tid] = 0.f; }
    if (tid < 64) {
        const float inv = 1.0f / (float)PTOT;
        int ce = tid << 1;
        float m0 = g_s1[ce] * inv;
        float v0 = g_s1[128 + ce] * inv - m0 * m0;
        float a0 = gam[ce] * rsqrtf(v0 + EPSV);
        float c0 = bet[ce] - m0 * a0;
        float m1 = g_s1[ce + 1] * inv;
        float v1 = g_s1[128 + ce + 1] * inv - m1 * m1;
        float a1 = gam[ce + 1] * rsqrtf(v1 + EPSV);
        float c1 = bet[ce + 1] - m1 * a1;
        __half2 ha = __floats2half2_rn(a0, a1);
        __half2 hc = __floats2half2_rn(c0, c1);
        sAC[tid] = make_uint2(*(uint32_t*)&ha, *(uint32_t*)&hc);
    }
    // W tile: rows nh..nh+127 of W2 (overlaps with async copies)
    for (int i = tid; i < 8192; i += 256) {
        int o = i >> 6, c2 = i & 63;
        *(uint32_t*)(sm + L2_WH + sw_pair(o, c2)) = g_W2h2[(nh + o)*64 + c2];
    }
    CP_WAIT0();
    __syncthreads();   // the ONLY barrier before compute

    int mr = (wid & 1) * 32, nr = (wid >> 1) * 32;
    int aRow = lane & 15, aSel = lane >> 4;
    int bRow = (lane & 7) + ((lane >> 4) << 3), bSel = (lane >> 3) & 1;

    #pragma unroll 1
    for (int t = 0; t < 4; t++) {
        uint32_t Ub = sb + L2_U + t * 16384;

        float acc[2][4][4];
        #pragma unroll
        for (int mt = 0; mt < 2; mt++)
            #pragma unroll
            for (int nt = 0; nt < 4; nt++)
                #pragma unroll
                for (int q = 0; q < 4; q++) acc[mt][nt][q] = 0.f;

        for (int ks = 0; ks < 8; ks++) {
            uint2 ac0 = sAC[8*ks + (lane & 3)];
            uint2 ac1 = sAC[8*ks + (lane & 3) + 4];
            uint32_t ah[2][4];
            int clA = 2*ks + aSel;
            #pragma unroll
            for (int mt = 0; mt < 2; mt++) {
                ldmx4(ah[mt], Ub + sw_chunk(mr + mt*16 + aRow, clA));
                ah[mt][0] = bn_lrelu2(ah[mt][0], ac0.x, ac0.y);
                ah[mt][1] = bn_lrelu2(ah[mt][1], ac0.x, ac0.y);
                ah[mt][2] = bn_lrelu2(ah[mt][2], ac1.x, ac1.y);
                ah[mt][3] = bn_lrelu2(ah[mt][3], ac1.x, ac1.y);
            }
            int clB = 2*ks + bSel;
            #pragma unroll
            for (int q = 0; q < 2; q++) {
                int n = nr + q*16 + bRow;
                uint32_t bh[4];
                ldmx4(bh, sb + L2_WH + sw_chunk(n, clB));
                #pragma unroll
                for (int mt = 0; mt < 2; mt++) {
                    mma16816(acc[mt][2*q],     ah[mt], bh);
                    mma16816(acc[mt][2*q + 1], ah[mt], bh + 2);
                }
            }
        }

        // ---- epilogue (no barriers) ----
        int pbase = (tb + t) * 64;
        int bn = (pbase >> 5) + (wid & 1);
        #pragma unroll
        for (int nt = 0; nt < 4; nt++) {
            float mx0 = fmaxf(fmaxf(acc[0][nt][0], acc[0][nt][2]),
                              fmaxf(acc[1][nt][0], acc[1][nt][2]));
            float mx1 = fmaxf(fmaxf(acc[0][nt][1], acc[0][nt][3]),
                              fmaxf(acc[1][nt][1], acc[1][nt][3]));
            float mn0 = fminf(fminf(acc[0][nt][0], acc[0][nt][2]),
                              fminf(acc[1][nt][0], acc[1][nt][2]));
            float mn1 = fminf(fminf(acc[0][nt][1], acc[0][nt][3]),
                              fminf(acc[1][nt][1], acc[1][nt][3]));
            float s0 = acc[0][nt][0] + acc[0][nt][2] + acc[1][nt][0] + acc[1][nt][2];
            float s1 = acc[0][nt][1] + acc[0][nt][3] + acc[1][nt][1] + acc[1][nt][3];
            float q0 = acc[0][nt][0]*acc[0][nt][0] + acc[0][nt][2]*acc[0][nt][2]
                     + acc[1][nt][0]*acc[1][nt][0] + acc[1][nt][2]*acc[1][nt][2];
            float q1 = acc[0][nt][1]*acc[0][nt][1] + acc[0][nt][3]*acc[0][nt][3]
                     + acc[1][nt][1]*acc[1][nt][1] + acc[1][nt][3]*acc[1][nt][3];
            #pragma unroll
            for (int d = 4; d < 32; d <<= 1) {
                mx0 = fmaxf(mx0, __shfl_xor_sync(0xFFFFFFFF, mx0, d));
                mx1 = fmaxf(mx1, __shfl_xor_sync(0xFFFFFFFF, mx1, d));
                mn0 = fminf(mn0, __shfl_xor_sync(0xFFFFFFFF, mn0, d));
                mn1 = fminf(mn1, __shfl_xor_sync(0xFFFFFFFF, mn1, d));
                s0 += __shfl_xor_sync(0xFFFFFFFF, s0, d);
                s1 += __shfl_xor_sync(0xFFFFFFFF, s1, d);
                q0 += __shfl_xor_sync(0xFFFFFFFF, q0, d);
                q1 += __shfl_xor_sync(0xFFFFFFFF, q1, d);
            }
            if (lane < 4) {
                int cl = nr + nt*8 + (lane << 1);
                int c  = nh + cl;
                *(float2*)&g_mx[bn*256 + c] = make_float2(mx0, mx1);
                *(float2*)&g_mn[bn*256 + c] = make_float2(mn0, mn1);
                atomicAdd(&sSum[cl], s0);  atomicAdd(&sSum[cl + 1], s1);
                atomicAdd(&sSs[cl],  q0);  atomicAdd(&sSs[cl + 1],  q1);
            }
        }
    }
    __syncthreads();
    if (tid < 128) {
        atomicAdd(&g_s2[nh + tid],       sSum[tid]);
        atomicAdd(&g_s2[256 + nh + tid], sSs[tid]);
    }
}

// ---------------- k_out ----------------
static const int SMEM_OUT = 2 * 64 * 257 * 4;
__global__ void __launch_bounds__(256) k_out(float* __restrict__ out,
        const float* __restrict__ gam, const float* __restrict__ bet) {
    extern __shared__ float smf[];
    float* sMx = smf;
    float* sMn = smf + 64*257;
    __shared__ float sA2[256], sC2[256];
    int tid = threadIdx.x;
    {
        const float inv = 1.0f / (float)PTOT;
        float mean = g_s2[tid] * inv;
        float var  = g_s2[256 + tid] * inv - mean * mean;
        float a = gam[tid] * rsqrtf(var + EPSV);
        sA2[tid] = a; sC2[tid] = bet[tid] - mean * a;
    }
    int b  = blockIdx.x >> 5;
    int n0 = (blockIdx.x & 31) * 64;
    for (int i = tid; i < 64*256; i += 256) {
        int nl = i >> 8, o = i & 255;
        int g = (b*NN + n0 + nl)*256 + o;
        sMx[nl*257 + o] = g_mx[g];
        sMn[nl*257 + o] = g_mn[g];
    }
    __syncthreads();
    for (int i = tid; i < 64*256; i += 256) {
        int o = i >> 6, nl = i & 63;
        float a = sA2[o], c = sC2[o];
        float z = (a >= 0.f) ? sMx[nl*257 + o] : sMn[nl*257 + o];
        float y = fmaf(a, z, c);
        out[(b*256 + o)*NN + n0 + nl] = (y > 0.f) ? y : SLOPE * y;
    }
}

// ---------------- launch ----------------
extern "C" void kernel_launch(void* const* d_in, const int* in_sizes, int n_in,
                              void* d_out, int out_size) {
    const float* pos1 = (const float*)d_in[0];
    const float* pos2 = (const float*)d_in[1];
    const float* f1   = (const float*)d_in[2];
    const float* f2   = (const float*)d_in[3];
    const int*   idxp = (const int*)d_in[4];
    const float* W0 = (const float*)d_in[5];
    const float* g0 = (const float*)d_in[6];
    const float* b0 = (const float*)d_in[7];
    const float* W1 = (const float*)d_in[8];
    const float* g1 = (const float*)d_in[9];
    const float* b1 = (const float*)d_in[10];
    const float* W2 = (const float*)d_in[11];
    const float* g2 = (const float*)d_in[12];
    const float* b2 = (const float*)d_in[13];

    cudaFuncSetAttribute(k_prep, cudaFuncAttributeMaxDynamicSharedMemorySize, SMEM_PREP);
    cudaFuncSetAttribute(k_l1,   cudaFuncAttributeMaxDynamicSharedMemorySize, SMEM_L1);
    cudaFuncSetAttribute(k_l2,   cudaFuncAttributeMaxDynamicSharedMemorySize, SMEM_L2);
    cudaFuncSetAttribute(k_out,  cudaFuncAttributeMaxDynamicSharedMemorySize, SMEM_OUT);

    float* outp = (float*)d_out;
    int featOff = out_size - BB*L2C*NN;
    if (featOff < 0) featOff = 0;

    k_prep<<<BB*(NN/16), 128, SMEM_PREP>>>(pos1, pos2, f1, f2, W0, W1, W2); // 0
    k_stats0<<<PTOT/128, 128>>>(idxp);                               // 1
    k_fold<<<512, 256>>>(g0, b0);                                    // 2
    k_l1<<<PTOT/256, 256, SMEM_L1>>>(idxp);                          // 3 (profiled)
    k_l2<<<2*(PTOT/256), 256, SMEM_L2>>>(g1, b1);                    // 4
    if (featOff > 0)
        cudaMemcpyAsync(d_out, pos1, (size_t)featOff * sizeof(float),
                        cudaMemcpyDeviceToDevice, 0);
    k_out<<<BB*(NN/64), 256, SMEM_OUT>>>(outp + featOff, g2, b2);    // 5
}

// round 17
// speedup vs baseline: 1.2011x; 1.2011x over previous
#include <cuda_runtime.h>
#include <cuda_fp16.h>
#include <cstdint>

#define BB 4
#define NN 2048
#define KK 32
#define L0 128
#define L1C 128
#define L2C 256
#define PTOT (BB*NN*KK)   /* 262144 */
#define EPSV 1e-5f
#define SLOPE 0.01f

// ---------------- scratch ----------------
__device__ __align__(16) float g_A[BB*NN*L0];              // 4 MB fp32
__device__ __align__(16) float g_D[BB*NN*L0];              // 4 MB fp32
__device__ __align__(16) uint32_t g_Ah[BB*NN*64];          // 2 MB : a0*A, half2 (folded)
__device__ __align__(16) uint32_t g_Dh[BB*NN*64];          // 2 MB : a0*D + c0, half2
__device__ __align__(16) char g_y1s[(size_t)4096*16384];   // 67 MB : y1, swizzled 16KB tiles
__device__ float g_mx[BB*NN*L2C];            // 8 MB
__device__ float g_mn[BB*NN*L2C];            // 8 MB
__device__ float g_s0[2*L0];
__device__ float g_s1[2*L1C];
__device__ float g_s2[2*L2C];
__device__ __align__(16) uint32_t g_W1h2[128*64];          // W1 fp16 half2
__device__ __align__(16) uint32_t g_W2h2[256*64];          // W2 fp16 half2

// ---------------- helpers ----------------
__device__ __forceinline__ uint32_t smem_u32(const void* p) {
    uint32_t a;
    asm("{ .reg .u64 t; cvta.to.shared.u64 t, %1; cvt.u32.u64 %0, t; }" : "=r"(a) : "l"(p));
    return a;
}
__device__ __forceinline__ void ldmx4(uint32_t* r, uint32_t addr) {
    asm volatile("ldmatrix.sync.aligned.m8n8.x4.shared.b16 {%0,%1,%2,%3}, [%4];"
                 : "=r"(r[0]), "=r"(r[1]), "=r"(r[2]), "=r"(r[3]) : "r"(addr));
}
__device__ __forceinline__ void mma16816(float* d, const uint32_t* a, const uint32_t* b) {
    asm volatile(
        "mma.sync.aligned.m16n8k16.row.col.f32.f16.f16.f32 "
        "{%0,%1,%2,%3}, {%4,%5,%6,%7}, {%8,%9}, {%0,%1,%2,%3};"
        : "+f"(d[0]), "+f"(d[1]), "+f"(d[2]), "+f"(d[3])
        : "r"(a[0]), "r"(a[1]), "r"(a[2]), "r"(a[3]), "r"(b[0]), "r"(b[1]));
}
__device__ __forceinline__ void cp16(uint32_t dst, const void* src) {
    asm volatile("cp.async.cg.shared.global [%0], [%1], 16;" :: "r"(dst), "l"(src));
}
#define CP_COMMIT() asm volatile("cp.async.commit_group;" ::: "memory")
#define CP_WAIT0()  asm volatile("cp.async.wait_group 0;" ::: "memory")
// tile rows are 256B (128 halves); XOR-swizzle 16B chunks within each 128B octant
__device__ __forceinline__ uint32_t sw_pair(int row, int c2) {   // c2 = half2 index 0..63
    return (uint32_t)row*256u + (uint32_t)(((c2 >> 2) ^ (row & 7)) << 4) + (uint32_t)((c2 & 3) << 2);
}
__device__ __forceinline__ uint32_t sw_chunk(int row, int cl) {  // cl = 16B chunk 0..15
    return (uint32_t)row*256u + (uint32_t)(((cl ^ (row & 7)) & 15) << 4);
}
__device__ __forceinline__ uint32_t add_lrelu2(uint32_t a, uint32_t d) {
    __half2 s = __hadd2(*(__half2*)&a, *(__half2*)&d);
    __half2 u = __hmax2(s, __hmul2(s, __float2half2_rn(SLOPE)));
    return *(uint32_t*)&u;
}
__device__ __forceinline__ uint32_t bn_lrelu2(uint32_t y, uint32_t a, uint32_t c) {
    __half2 u = __hfma2(*(__half2*)&a, *(__half2*)&y, *(__half2*)&c);
    __half2 r = __hmax2(u, __hmul2(u, __float2half2_rn(SLOPE)));
    return *(uint32_t*)&r;
}

// ---------------- k_prep: A/D factorization, 32-pt tiles + absorbed zero/W-split ----------------
#define SW_PITCH 16900   /* 131*129=16899 rounded up so sI is 16B-aligned */
static const int SMEM_PREP = (SW_PITCH + 131*32) * 4;
__global__ void __launch_bounds__(128) k_prep(
        const float* __restrict__ pos1, const float* __restrict__ pos2,
        const float* __restrict__ f1,   const float* __restrict__ f2,
        const float* __restrict__ W0,
        const float* __restrict__ W1,   const float* __restrict__ W2) {
    extern __shared__ float sp[];
    float* sW = sp;               // [131][129]
    float* sI = sp + SW_PITCH;    // [131][32], 16B-aligned
    int blk = blockIdx.x;
    int b  = blk / (NN/32);
    int j0 = (blk % (NN/32)) * 32;
    int tid = threadIdx.x;

    if (blk == 0) {
        for (int j = tid; j < 1024; j += 128) {
            if (j < 256)      g_s0[j] = 0.f;
            else if (j < 512) g_s1[j - 256] = 0.f;
            else              g_s2[j - 512] = 0.f;
        }
    }
    if (blk < 96) {
        for (int t2 = tid; t2 < 256; t2 += 128) {
            int i = blk * 256 + t2;
            if (i < 8192) {
                float2 w = ((const float2*)W1)[i];
                __half2 h = __floats2half2_rn(w.x, w.y);
                g_W1h2[i] = *(uint32_t*)&h;
            } else if (i < 24576) {
                int j = i - 8192;
                float2 w = ((const float2*)W2)[j];
                __half2 h = __floats2half2_rn(w.x, w.y);
                g_W2h2[j] = *(uint32_t*)&h;
            }
        }
    }

    // ---- pass A ----
    for (int i = tid; i < 131*128; i += 128) {
        int o = i / 131, c = i - o*131;
        sW[c*129 + o] = W0[o*259 + c];
    }
    for (int i = tid; i < 131*32; i += 128) {
        int c = i >> 5, jl = i & 31;
        sI[c*32 + jl] = (c < 3) ? pos2[(b*3 + c)*NN + j0 + jl]
                                : f2[(b*128 + (c-3))*NN + j0 + jl];
    }
    __syncthreads();
    {
        float4 acc[8];
        #pragma unroll
        for (int q = 0; q < 8; q++) acc[q] = make_float4(0.f,0.f,0.f,0.f);
        for (int c = 0; c < 131; c++) {
            float wv = sW[c*129 + tid];
            const float4* r = (const float4*)&sI[c*32];
            #pragma unroll
            for (int q = 0; q < 8; q++) {
                float4 rv = r[q];
                acc[q].x = fmaf(wv, rv.x, acc[q].x);
                acc[q].y = fmaf(wv, rv.y, acc[q].y);
                acc[q].z = fmaf(wv, rv.z, acc[q].z);
                acc[q].w = fmaf(wv, rv.w, acc[q].w);
            }
        }
        const float* af = (const float*)acc;
        #pragma unroll
        for (int pt = 0; pt < 32; pt++)
            g_A[((b*NN + j0 + pt) << 7) + tid] = af[pt];
    }
    __syncthreads();

    // ---- pass D ----
    for (int i = tid; i < 131*128; i += 128) {
        int o = i / 131, c = i - o*131;
        int src = (c < 3) ? c : 128 + c;   // 131 + (c-3)
        sW[c*129 + o] = W0[o*259 + src];
    }
    for (int i = tid; i < 131*32; i += 128) {
        int c = i >> 5, jl = i & 31;
        sI[c*32 + jl] = (c < 3) ? -pos1[(b*3 + c)*NN + j0 + jl]
                                : f1[(b*128 + (c-3))*NN + j0 + jl];
    }
    __syncthreads();
    {
        float4 acc[8];
        #pragma unroll
        for (int q = 0; q < 8; q++) acc[q] = make_float4(0.f,0.f,0.f,0.f);
        for (int c = 0; c < 131; c++) {
            float wv = sW[c*129 + tid];
            const float4* r = (const float4*)&sI[c*32];
            #pragma unroll
            for (int q = 0; q < 8; q++) {
                float4 rv = r[q];
                acc[q].x = fmaf(wv, rv.x, acc[q].x);
                acc[q].y = fmaf(wv, rv.y, acc[q].y);
                acc[q].z = fmaf(wv, rv.z, acc[q].z);
                acc[q].w = fmaf(wv, rv.w, acc[q].w);
            }
        }
        const float* af = (const float*)acc;
        #pragma unroll
        for (int pt = 0; pt < 32; pt++)
            g_D[((b*NN + j0 + pt) << 7) + tid] = af[pt];
    }
}

// ---------------- k_stats0: stats of y0 = A[idx] + D (R11 exact form) ----------------
__global__ void __launch_bounds__(128) k_stats0(const int* __restrict__ idxp) {
    __shared__ int s_idx[128];
    int tid = threadIdx.x;
    int pbase = blockIdx.x * 128;
    s_idx[tid] = idxp[pbase + tid];
    __syncthreads();
    float s = 0.f, ss = 0.f;
    #pragma unroll 4
    for (int i = 0; i < 128; i++) {
        int p = pbase + i;
        int arow = ((p >> 16) * NN + s_idx[i]) << 7;
        int drow = (p >> 5) << 7;
        float y = g_A[arow + tid] + g_D[drow + tid];
        s += y; ss = fmaf(y, y, ss);
    }
    atomicAdd(&g_s0[tid], s);
    atomicAdd(&g_s0[L0 + tid], ss);
}

// ---------------- k_fold: A~ = a0*A (half2), D~ = a0*D + c0 (half2) ----------------
__global__ void __launch_bounds__(256) k_fold(
        const float* __restrict__ gam, const float* __restrict__ bet) {
    __shared__ float sA[128], sC[128];
    int tid = threadIdx.x;
    if (tid < 128) {
        const float inv = 1.0f / (float)PTOT;
        float mean = g_s0[tid] * inv;
        float var  = g_s0[128 + tid] * inv - mean * mean;
        float a = gam[tid] * rsqrtf(var + EPSV);
        sA[tid] = a; sC[tid] = bet[tid] - mean * a;
    }
    __syncthreads();
    int q = blockIdx.x * 256 + tid;     // quad index over BB*NN*16
    int row = q >> 4, ch = q & 15;
    int c = ch << 3;
    const float4* a4 = (const float4*)(g_A + (row << 7) + c);
    const float4* d4 = (const float4*)(g_D + (row << 7) + c);
    float4 av0 = a4[0], av1 = a4[1], dv0 = d4[0], dv1 = d4[1];
    uint4 oa, od;
    {
        __half2 h;
        h = __floats2half2_rn(sA[c+0]*av0.x, sA[c+1]*av0.y); oa.x = *(uint32_t*)&h;
        h = __floats2half2_rn(sA[c+2]*av0.z, sA[c+3]*av0.w); oa.y = *(uint32_t*)&h;
        h = __floats2half2_rn(sA[c+4]*av1.x, sA[c+5]*av1.y); oa.z = *(uint32_t*)&h;
        h = __floats2half2_rn(sA[c+6]*av1.z, sA[c+7]*av1.w); oa.w = *(uint32_t*)&h;
        h = __floats2half2_rn(fmaf(sA[c+0],dv0.x,sC[c+0]), fmaf(sA[c+1],dv0.y,sC[c+1])); od.x = *(uint32_t*)&h;
        h = __floats2half2_rn(fmaf(sA[c+2],dv0.z,sC[c+2]), fmaf(sA[c+3],dv0.w,sC[c+3])); od.y = *(uint32_t*)&h;
        h = __floats2half2_rn(fmaf(sA[c+4],dv1.x,sC[c+4]), fmaf(sA[c+5],dv1.y,sC[c+5])); od.z = *(uint32_t*)&h;
        h = __floats2half2_rn(fmaf(sA[c+6],dv1.z,sC[c+6]), fmaf(sA[c+7],dv1.w,sC[c+7])); od.w = *(uint32_t*)&h;
    }
    *(uint4*)&g_Ah[(row << 6) + (ch << 2)] = oa;
    *(uint4*)&g_Dh[(row << 6) + (ch << 2)] = od;
}

// ======================= layer 1 (R11 exact) =======================
// block: 4 tiles x (64 pts x 128 out); 256 thr / 8 warps; 3 CTAs/SM
static const int L1_UH = 4096;                // 16384
static const int L1_WH = L1_UH + 16384;       // 32768
static const int SMEM_L1 = L1_WH + 32768;     // 53248

__global__ void __launch_bounds__(256, 3) k_l1(const int* __restrict__ idxp) {
    extern __shared__ char sm[];
    uint32_t sb = smem_u32(sm);
    int*   sAR  = (int*)(sm);            // 256 ints
    float* sSum = (float*)(sm + 1024);   // 128
    float* sSs  = (float*)(sm + 1536);   // 128
    int tid = threadIdx.x, wid = tid >> 5, lane = tid & 31;
    int pblk = blockIdx.x * 256;

    if (tid < 128) { sSum[tid] = 0.f; sSs[tid] = 0.f; }
    {
        int p = pblk + tid;
        sAR[tid] = ((p >> 16) * NN + idxp[p]) << 6;
    }
    __syncthreads();

    for (int i = tid; i < 8192; i += 256) {
        int o = i >> 6, c2 = i & 63;
        *(uint32_t*)(sm + L1_WH + sw_pair(o, c2)) = g_W1h2[i];
    }

    int mr = (wid & 3) * 16, nr = (wid >> 2) * 64;
    int aRow = lane & 15, aSel = lane >> 4;
    int bRow = (lane & 7) + ((lane >> 4) << 3), bSel = (lane >> 3) & 1;
    int fch = tid & 15, fpl = tid >> 4;

    #pragma unroll 1
    for (int t = 0; t < 4; t++) {
        int pbase = pblk + t * 64;
        if (t) __syncthreads();

        #pragma unroll
        for (int it = 0; it < 4; it++) {
            int pl = fpl + it * 16;
            uint4 av = *(const uint4*)&g_Ah[sAR[t*64 + pl] + (fch << 2)];
            uint4 dv = *(const uint4*)&g_Dh[(((pbase + pl) >> 5) << 6) + (fch << 2)];
            uint4 o;
            o.x = add_lrelu2(av.x, dv.x);
            o.y = add_lrelu2(av.y, dv.y);
            o.z = add_lrelu2(av.z, dv.z);
            o.w = add_lrelu2(av.w, dv.w);
            *(uint4*)(sm + L1_UH + sw_chunk(pl, fch)) = o;
        }
        __syncthreads();

        float acc[8][4];
        #pragma unroll
        for (int nt = 0; nt < 8; nt++)
            #pragma unroll
            for (int q = 0; q < 4; q++) acc[nt][q] = 0.f;

        for (int ks = 0; ks < 8; ks++) {
            uint32_t ah[4];
            int clA = 2*ks + aSel;
            ldmx4(ah, sb + L1_UH + sw_chunk(mr + aRow, clA));
            int clB = 2*ks + bSel;
            #pragma unroll
            for (int q = 0; q < 4; q++) {
                int n = nr + q*16 + bRow;
                uint32_t bh[4];
                ldmx4(bh, sb + L1_WH + sw_chunk(n, clB));
                mma16816(acc[2*q],     ah, bh);
                mma16816(acc[2*q + 1], ah, bh + 2);
            }
        }

        // ---- epilogue: y1 -> swizzled tile in g_y1s + channel sums ----
        {
            int r = mr + (lane >> 2);
            char* yb = g_y1s + ((size_t)(pbase >> 6)) * 16384;
            #pragma unroll
            for (int nt = 0; nt < 8; nt++) {
                int c2 = (nr >> 1) + nt*4 + (lane & 3);
                __half2 h0 = __floats2half2_rn(acc[nt][0], acc[nt][1]);
                __half2 h1 = __floats2half2_rn(acc[nt][2], acc[nt][3]);
                *(uint32_t*)(yb + sw_pair(r, c2))     = *(uint32_t*)&h0;
                *(uint32_t*)(yb + sw_pair(r + 8, c2)) = *(uint32_t*)&h1;
            }
        }
        #pragma unroll
        for (int nt = 0; nt < 8; nt++) {
            float s0 = acc[nt][0] + acc[nt][2];
            float s1 = acc[nt][1] + acc[nt][3];
            float q0 = acc[nt][0]*acc[nt][0] + acc[nt][2]*acc[nt][2];
            float q1 = acc[nt][1]*acc[nt][1] + acc[nt][3]*acc[nt][3];
            #pragma unroll
            for (int d = 4; d < 32; d <<= 1) {
                s0 += __shfl_xor_sync(0xFFFFFFFF, s0, d);
                s1 += __shfl_xor_sync(0xFFFFFFFF, s1, d);
                q0 += __shfl_xor_sync(0xFFFFFFFF, q0, d);
                q1 += __shfl_xor_sync(0xFFFFFFFF, q1, d);
            }
            if (lane < 4) {
                int c = nr + nt*8 + (lane << 1);
                atomicAdd(&sSum[c], s0);  atomicAdd(&sSum[c + 1], s1);
                atomicAdd(&sSs[c],  q0);  atomicAdd(&sSs[c + 1],  q1);
            }
        }
    }
    __syncthreads();
    if (tid < 128) {
        atomicAdd(&g_s1[tid],       sSum[tid]);
        atomicAdd(&g_s1[128 + tid], sSs[tid]);
    }
}

// ======================= layer 2 (R11 exact: fragment BN, cp.async double-buffer) =======================
static const int L2_U0 = 4096;
static const int L2_U1 = L2_U0 + 16384;       // 20480
static const int L2_WH = L2_U1 + 16384;       // 36864
static const int SMEM_L2 = L2_WH + 32768;     // 69632

__global__ void __launch_bounds__(256, 3) k_l2(
        const float* __restrict__ gam, const float* __restrict__ bet) {
    extern __shared__ char sm[];
    uint32_t sb = smem_u32(sm);
    uint2* sAC  = (uint2*)(sm);          // 64 x {a half2, c half2}
    float* sSum = (float*)(sm + 512);    // 128
    float* sSs  = (float*)(sm + 1024);   // 128
    int tid = threadIdx.x, wid = tid >> 5, lane = tid & 31;
    int tb = (blockIdx.x >> 1) * 4;      // tile base (64-pt tiles)
    int nh = (blockIdx.x & 1) * 128;

    if (tid < 128) { sSum[tid] = 0.f; sSs[tid] = 0.f; }
    if (tid < 64) {
        const float inv = 1.0f / (float)PTOT;
        int ce = tid << 1;
        float m0 = g_s1[ce] * inv;
        float v0 = g_s1[128 + ce] * inv - m0 * m0;
        float a0 = gam[ce] * rsqrtf(v0 + EPSV);
        float c0 = bet[ce] - m0 * a0;
        float m1 = g_s1[ce + 1] * inv;
        float v1 = g_s1[128 + ce + 1] * inv - m1 * m1;
        float a1 = gam[ce + 1] * rsqrtf(v1 + EPSV);
        float c1 = bet[ce + 1] - m1 * a1;
        __half2 ha = __floats2half2_rn(a0, a1);
        __half2 hc = __floats2half2_rn(c0, c1);
        sAC[tid] = make_uint2(*(uint32_t*)&ha, *(uint32_t*)&hc);
    }

    // prologue: async-copy tile tb into U0
    {
        uint32_t dst = sb + L2_U0 + tid * 16;
        const char* src = g_y1s + (size_t)tb * 16384 + tid * 16;
        #pragma unroll
        for (int k2 = 0; k2 < 4; k2++) cp16(dst + k2*4096, src + k2*4096);
        CP_COMMIT();
    }
    // W tile: rows nh..nh+127 of W2 (overlaps with async copy)
    for (int i = tid; i < 8192; i += 256) {
        int o = i >> 6, c2 = i & 63;
        *(uint32_t*)(sm + L2_WH + sw_pair(o, c2)) = g_W2h2[(nh + o)*64 + c2];
    }
    __syncthreads();

    int mr = (wid & 1) * 32, nr = (wid >> 1) * 32;
    int aRow = lane & 15, aSel = lane >> 4;
    int bRow = (lane & 7) + ((lane >> 4) << 3), bSel = (lane >> 3) & 1;

    #pragma unroll 1
    for (int t = 0; t < 4; t++) {
        CP_WAIT0();
        __syncthreads();
        if (t < 3) {   // prefetch next tile into the other buffer
            uint32_t dst = sb + (((t + 1) & 1) ? L2_U1 : L2_U0) + tid * 16;
            const char* src = g_y1s + (size_t)(tb + t + 1) * 16384 + tid * 16;
            #pragma unroll
            for (int k2 = 0; k2 < 4; k2++) cp16(dst + k2*4096, src + k2*4096);
            CP_COMMIT();
        }
        uint32_t Ub = sb + ((t & 1) ? L2_U1 : L2_U0);

        float acc[2][4][4];
        #pragma unroll
        for (int mt = 0; mt < 2; mt++)
            #pragma unroll
            for (int nt = 0; nt < 4; nt++)
                #pragma unroll
                for (int q = 0; q < 4; q++) acc[mt][nt][q] = 0.f;

        for (int ks = 0; ks < 8; ks++) {
            uint2 ac0 = sAC[8*ks + (lane & 3)];
            uint2 ac1 = sAC[8*ks + (lane & 3) + 4];
            uint32_t ah[2][4];
            int clA = 2*ks + aSel;
            #pragma unroll
            for (int mt = 0; mt < 2; mt++) {
                ldmx4(ah[mt], Ub + sw_chunk(mr + mt*16 + aRow, clA));
                ah[mt][0] = bn_lrelu2(ah[mt][0], ac0.x, ac0.y);
                ah[mt][1] = bn_lrelu2(ah[mt][1], ac0.x, ac0.y);
                ah[mt][2] = bn_lrelu2(ah[mt][2], ac1.x, ac1.y);
                ah[mt][3] = bn_lrelu2(ah[mt][3], ac1.x, ac1.y);
            }
            int clB = 2*ks + bSel;
            #pragma unroll
            for (int q = 0; q < 2; q++) {
                int n = nr + q*16 + bRow;
                uint32_t bh[4];
                ldmx4(bh, sb + L2_WH + sw_chunk(n, clB));
                #pragma unroll
                for (int mt = 0; mt < 2; mt++) {
                    mma16816(acc[mt][2*q],     ah[mt], bh);
                    mma16816(acc[mt][2*q + 1], ah[mt], bh + 2);
                }
            }
        }

        // ---- register epilogue: warp owns one K-group (32 pts) x 32 ch ----
        int pbase = (tb + t) * 64;
        int bn = (pbase >> 5) + (wid & 1);
        #pragma unroll
        for (int nt = 0; nt < 4; nt++) {
            float mx0 = fmaxf(fmaxf(acc[0][nt][0], acc[0][nt][2]),
                              fmaxf(acc[1][nt][0], acc[1][nt][2]));
            float mx1 = fmaxf(fmaxf(acc[0][nt][1], acc[0][nt][3]),
                              fmaxf(acc[1][nt][1], acc[1][nt][3]));
            float mn0 = fminf(fminf(acc[0][nt][0], acc[0][nt][2]),
                              fminf(acc[1][nt][0], acc[1][nt][2]));
            float mn1 = fminf(fminf(acc[0][nt][1], acc[0][nt][3]),
                              fminf(acc[1][nt][1], acc[1][nt][3]));
            float s0 = acc[0][nt][0] + acc[0][nt][2] + acc[1][nt][0] + acc[1][nt][2];
            float s1 = acc[0][nt][1] + acc[0][nt][3] + acc[1][nt][1] + acc[1][nt][3];
            float q0 = acc[0][nt][0]*acc[0][nt][0] + acc[0][nt][2]*acc[0][nt][2]
                     + acc[1][nt][0]*acc[1][nt][0] + acc[1][nt][2]*acc[1][nt][2];
            float q1 = acc[0][nt][1]*acc[0][nt][1] + acc[0][nt][3]*acc[0][nt][3]
                     + acc[1][nt][1]*acc[1][nt][1] + acc[1][nt][3]*acc[1][nt][3];
            #pragma unroll
            for (int d = 4; d < 32; d <<= 1) {
                mx0 = fmaxf(mx0, __shfl_xor_sync(0xFFFFFFFF, mx0, d));
                mx1 = fmaxf(mx1, __shfl_xor_sync(0xFFFFFFFF, mx1, d));
                mn0 = fminf(mn0, __shfl_xor_sync(0xFFFFFFFF, mn0, d));
                mn1 = fminf(mn1, __shfl_xor_sync(0xFFFFFFFF, mn1, d));
                s0 += __shfl_xor_sync(0xFFFFFFFF, s0, d);
                s1 += __shfl_xor_sync(0xFFFFFFFF, s1, d);
                q0 += __shfl_xor_sync(0xFFFFFFFF, q0, d);
                q1 += __shfl_xor_sync(0xFFFFFFFF, q1, d);
            }
            if (lane < 4) {
                int cl = nr + nt*8 + (lane << 1);
                int c  = nh + cl;
                *(float2*)&g_mx[bn*256 + c] = make_float2(mx0, mx1);
                *(float2*)&g_mn[bn*256 + c] = make_float2(mn0, mn1);
                atomicAdd(&sSum[cl], s0);  atomicAdd(&sSum[cl + 1], s1);
                atomicAdd(&sSs[cl],  q0);  atomicAdd(&sSs[cl + 1],  q1);
            }
        }
    }
    __syncthreads();
    if (tid < 128) {
        atomicAdd(&g_s2[nh + tid],       sSum[tid]);
        atomicAdd(&g_s2[256 + nh + tid], sSs[tid]);
    }
}

// ---------------- k_out ----------------
static const int SMEM_OUT = 2 * 64 * 257 * 4;
__global__ void __launch_bounds__(256) k_out(float* __restrict__ out,
        const float* __restrict__ gam, const float* __restrict__ bet) {
    extern __shared__ float smf[];
    float* sMx = smf;
    float* sMn = smf + 64*257;
    __shared__ float sA2[256], sC2[256];
    int tid = threadIdx.x;
    {
        const float inv = 1.0f / (float)PTOT;
        float mean = g_s2[tid] * inv;
        float var  = g_s2[256 + tid] * inv - mean * mean;
        float a = gam[tid] * rsqrtf(var + EPSV);
        sA2[tid] = a; sC2[tid] = bet[tid] - mean * a;
    }
    int b  = blockIdx.x >> 5;
    int n0 = (blockIdx.x & 31) * 64;
    for (int i = tid; i < 64*256; i += 256) {
        int nl = i >> 8, o = i & 255;
        int g = (b*NN + n0 + nl)*256 + o;
        sMx[nl*257 + o] = g_mx[g];
        sMn[nl*257 + o] = g_mn[g];
    }
    __syncthreads();
    for (int i = tid; i < 64*256; i += 256) {
        int o = i >> 6, nl = i & 63;
        float a = sA2[o], c = sC2[o];
        float z = (a >= 0.f) ? sMx[nl*257 + o] : sMn[nl*257 + o];
        float y = fmaf(a, z, c);
        out[(b*256 + o)*NN + n0 + nl] = (y > 0.f) ? y : SLOPE * y;
    }
}

// ---------------- launch ----------------
extern "C" void kernel_launch(void* const* d_in, const int* in_sizes, int n_in,
                              void* d_out, int out_size) {
    const float* pos1 = (const float*)d_in[0];
    const float* pos2 = (const float*)d_in[1];
    const float* f1   = (const float*)d_in[2];
    const float* f2   = (const float*)d_in[3];
    const int*   idxp = (const int*)d_in[4];
    const float* W0 = (const float*)d_in[5];
    const float* g0 = (const float*)d_in[6];
    const float* b0 = (const float*)d_in[7];
    const float* W1 = (const float*)d_in[8];
    const float* g1 = (const float*)d_in[9];
    const float* b1 = (const float*)d_in[10];
    const float* W2 = (const float*)d_in[11];
    const float* g2 = (const float*)d_in[12];
    const float* b2 = (const float*)d_in[13];

    cudaFuncSetAttribute(k_prep, cudaFuncAttributeMaxDynamicSharedMemorySize, SMEM_PREP);
    cudaFuncSetAttribute(k_l1,   cudaFuncAttributeMaxDynamicSharedMemorySize, SMEM_L1);
    cudaFuncSetAttribute(k_l2,   cudaFuncAttributeMaxDynamicSharedMemorySize, SMEM_L2);
    cudaFuncSetAttribute(k_out,  cudaFuncAttributeMaxDynamicSharedMemorySize, SMEM_OUT);

    float* outp = (float*)d_out;
    int featOff = out_size - BB*L2C*NN;
    if (featOff < 0) featOff = 0;

    k_prep<<<BB*(NN/32), 128, SMEM_PREP>>>(pos1, pos2, f1, f2, W0, W1, W2); // 0
    k_stats0<<<PTOT/128, 128>>>(idxp);                               // 1
    k_fold<<<512, 256>>>(g0, b0);                                    // 2
    k_l1<<<PTOT/256, 256, SMEM_L1>>>(idxp);                          // 3 (profiled)
    k_l2<<<2*(PTOT/256), 256, SMEM_L2>>>(g1, b1);                    // 4
    if (featOff > 0)
        cudaMemcpyAsync(d_out, pos1, (size_t)featOff * sizeof(float),
                        cudaMemcpyDeviceToDevice, 0);
    k_out<<<BB*(NN/64), 256, SMEM_OUT>>>(outp + featOff, g2, b2);    // 5
}